// round 14
// baseline (speedup 1.0000x reference)
#include <cuda_runtime.h>
#include <math.h>

#define NMAX 100000

__device__ float    g_diag[NMAX];
__device__ unsigned g_deg[NMAX];

// ---------------------------------------------------------------------------
// K1 (heterogeneous): interleaved diag-GEMV blocks and deg+copy blocks.
//   diag block: 8 warps x 4 rows = 32 rows of x (DRAM-bound, MLP_p1=8)
//   deg  block: 256 threads x int4 = 1024 edges (LTS-atomic + idx copy)
//   When GDIAG == GDEG: even bid -> diag, odd -> deg.
// ---------------------------------------------------------------------------
__global__ void __launch_bounds__(256)
k_fused(const float* __restrict__ x,
        const float* __restrict__ w,
        const float* __restrict__ b,
        int n,
        const int* __restrict__ ei,
        float* __restrict__ out_idx,
        int E, int E4, int write_idx,
        int GDIAG, int GDEG, int interleave) {
    int bid = blockIdx.x;
    int is_diag, sub;
    if (interleave) {                 // GDIAG == GDEG, even/odd split
        is_diag = !(bid & 1);
        sub = bid >> 1;
    } else {
        if (bid < GDIAG) { is_diag = 1; sub = bid; }
        else             { is_diag = 0; sub = bid - GDIAG; }
    }

    if (is_diag) {
        // ---------------- diag portion: 4 rows per warp ----------------
        if (sub >= GDIAG) return;
        __shared__ float4 ws[64];
        int t = threadIdx.x;
        if (t < 64) ws[t] = ((const float4*)w)[t];
        __syncthreads();

        int lane = t & 31;
        int warp = sub * 8 + (t >> 5);
        int row0 = warp << 2;
        if (row0 >= n) return;

        const float4* xr0 = (const float4*)(x + (size_t)row0 * 256);
        const float4* xr1 = xr0 + 64;
        const float4* xr2 = xr0 + 128;
        const float4* xr3 = xr0 + 192;
        bool h1 = row0 + 1 < n, h2 = row0 + 2 < n, h3 = row0 + 3 < n;

        float4 z = make_float4(0, 0, 0, 0);
        // front-batched 8 independent loads
        float4 a0 = xr0[lane];
        float4 a1 = xr0[lane + 32];
        float4 b0 = h1 ? xr1[lane] : z;
        float4 b1 = h1 ? xr1[lane + 32] : z;
        float4 c0 = h2 ? xr2[lane] : z;
        float4 c1 = h2 ? xr2[lane + 32] : z;
        float4 d0 = h3 ? xr3[lane] : z;
        float4 d1 = h3 ? xr3[lane + 32] : z;

        float4 w0 = ws[lane];
        float4 w1 = ws[lane + 32];

        float s0 = a0.x*w0.x + a0.y*w0.y + a0.z*w0.z + a0.w*w0.w
                 + a1.x*w1.x + a1.y*w1.y + a1.z*w1.z + a1.w*w1.w;
        float s1 = b0.x*w0.x + b0.y*w0.y + b0.z*w0.z + b0.w*w0.w
                 + b1.x*w1.x + b1.y*w1.y + b1.z*w1.z + b1.w*w1.w;
        float s2 = c0.x*w0.x + c0.y*w0.y + c0.z*w0.z + c0.w*w0.w
                 + c1.x*w1.x + c1.y*w1.y + c1.z*w1.z + c1.w*w1.w;
        float s3 = d0.x*w0.x + d0.y*w0.y + d0.z*w0.z + d0.w*w0.w
                 + d1.x*w1.x + d1.y*w1.y + d1.z*w1.z + d1.w*w1.w;

#pragma unroll
        for (int o = 16; o; o >>= 1) {
            s0 += __shfl_xor_sync(0xffffffffu, s0, o);
            s1 += __shfl_xor_sync(0xffffffffu, s1, o);
            s2 += __shfl_xor_sync(0xffffffffu, s2, o);
            s3 += __shfl_xor_sync(0xffffffffu, s3, o);
        }
        if (lane == 0) {
            float bb = b[0];
            g_diag[row0] = 1.0f / (1.0f + expf(-(s0 + bb)));
            if (h1) g_diag[row0 + 1] = 1.0f / (1.0f + expf(-(s1 + bb)));
            if (h2) g_diag[row0 + 2] = 1.0f / (1.0f + expf(-(s2 + bb)));
            if (h3) g_diag[row0 + 3] = 1.0f / (1.0f + expf(-(s3 + bb)));
        }
    } else {
        // ---------------- deg + idx-copy portion ----------------
        int i = sub * 256 + threadIdx.x;
        if (i >= E4) return;
        int4 c = ((const int4*)(ei + E))[i];
        if (write_idx) {
            int4 r = ((const int4*)ei)[i];
            ((float4*)out_idx)[i] =
                make_float4((float)r.x, (float)r.y, (float)r.z, (float)r.w);
            ((float4*)(out_idx + E))[i] =
                make_float4((float)c.x, (float)c.y, (float)c.z, (float)c.w);
        }
        if ((unsigned)c.x < NMAX) atomicAdd(&g_deg[c.x], 1u);
        if ((unsigned)c.y < NMAX) atomicAdd(&g_deg[c.y], 1u);
        if ((unsigned)c.z < NMAX) atomicAdd(&g_deg[c.z], 1u);
        if ((unsigned)c.w < NMAX) atomicAdd(&g_deg[c.w], 1u);
    }
}

// ---------------------------------------------------------------------------
// K2: val[e] = attr[e] * diag[col] * rcp((float)deg[row]); 8 edges/thread.
// ---------------------------------------------------------------------------
__global__ void __launch_bounds__(256)
k_val(const int* __restrict__ ei,
      const float* __restrict__ attr,
      float* __restrict__ outv,
      int E8, int E) {
    int i = blockIdx.x * blockDim.x + threadIdx.x;
    if (i >= E8) return;

    const int4* rows4 = (const int4*)ei;
    const int4* cols4 = (const int4*)(ei + E);
    const float4* attr4 = (const float4*)attr;

    // front-batch 6 streaming loads
    int4 r0 = rows4[2 * i], r1 = rows4[2 * i + 1];
    int4 c0 = cols4[2 * i], c1 = cols4[2 * i + 1];
    float4 a0 = attr4[2 * i], a1 = attr4[2 * i + 1];

    // 16 independent gathers
    unsigned u0 = ((unsigned)r0.x < NMAX) ? g_deg[r0.x] : 1u;
    unsigned u1 = ((unsigned)r0.y < NMAX) ? g_deg[r0.y] : 1u;
    unsigned u2 = ((unsigned)r0.z < NMAX) ? g_deg[r0.z] : 1u;
    unsigned u3 = ((unsigned)r0.w < NMAX) ? g_deg[r0.w] : 1u;
    unsigned u4 = ((unsigned)r1.x < NMAX) ? g_deg[r1.x] : 1u;
    unsigned u5 = ((unsigned)r1.y < NMAX) ? g_deg[r1.y] : 1u;
    unsigned u6 = ((unsigned)r1.z < NMAX) ? g_deg[r1.z] : 1u;
    unsigned u7 = ((unsigned)r1.w < NMAX) ? g_deg[r1.w] : 1u;
    float g0 = ((unsigned)c0.x < NMAX) ? g_diag[c0.x] : 0.0f;
    float g1 = ((unsigned)c0.y < NMAX) ? g_diag[c0.y] : 0.0f;
    float g2 = ((unsigned)c0.z < NMAX) ? g_diag[c0.z] : 0.0f;
    float g3 = ((unsigned)c0.w < NMAX) ? g_diag[c0.w] : 0.0f;
    float g4 = ((unsigned)c1.x < NMAX) ? g_diag[c1.x] : 0.0f;
    float g5 = ((unsigned)c1.y < NMAX) ? g_diag[c1.y] : 0.0f;
    float g6 = ((unsigned)c1.z < NMAX) ? g_diag[c1.z] : 0.0f;
    float g7 = ((unsigned)c1.w < NMAX) ? g_diag[c1.w] : 0.0f;

    float4 v0, v1;
    v0.x = a0.x * g0 * __frcp_rn(__uint2float_rn(u0));
    v0.y = a0.y * g1 * __frcp_rn(__uint2float_rn(u1));
    v0.z = a0.z * g2 * __frcp_rn(__uint2float_rn(u2));
    v0.w = a0.w * g3 * __frcp_rn(__uint2float_rn(u3));
    v1.x = a1.x * g4 * __frcp_rn(__uint2float_rn(u4));
    v1.y = a1.y * g5 * __frcp_rn(__uint2float_rn(u5));
    v1.z = a1.z * g6 * __frcp_rn(__uint2float_rn(u6));
    v1.w = a1.w * g7 * __frcp_rn(__uint2float_rn(u7));
    ((float4*)outv)[2 * i]     = v0;
    ((float4*)outv)[2 * i + 1] = v1;
}

// ---------------------------------------------------------------------------
static void* g_deg_addr = nullptr;

extern "C" void kernel_launch(void* const* d_in, const int* in_sizes, int n_in,
                              void* d_out, int out_size) {
    const float* x    = (const float*)d_in[0];
    const int*   ei   = (const int*)d_in[1];     // int32 (2, E)
    const float* attr = (const float*)d_in[2];
    const float* w    = (const float*)d_in[3];
    const float* b    = (const float*)d_in[4];

    const int E  = in_sizes[2];
    const int Dd = in_sizes[3];
    const int n  = in_sizes[0] / Dd;

    if (!g_deg_addr) cudaGetSymbolAddress(&g_deg_addr, g_deg);

    float* out = (float*)d_out;
    float* out_vals;
    int write_idx;
    if (out_size >= 3 * E) {      // [edge_index(2E) | vals(E)] as float32
        write_idx = 1;
        out_vals = out + 2 * (size_t)E;
    } else {
        write_idx = 0;
        out_vals = out;
    }

    const int T = 256;
    const int E4 = E >> 2;
    const int E8 = E >> 3;

    const int GDIAG = (n + 31) / 32;          // 32 rows per diag block
    const int GDEG  = (E4 + T - 1) / T;       // 1024 edges per deg block
    const int interleave = (GDIAG == GDEG);
    const int GRID = GDIAG + GDEG;

    // zero degree counters via graph memset node (no kernel-launch floor)
    cudaMemsetAsync(g_deg_addr, 0, (size_t)n * sizeof(unsigned), 0);

    k_fused<<<GRID, T>>>(x, w, b, n, ei, out, E, E4, write_idx,
                         GDIAG, GDEG, interleave);
    k_val<<<(E8 + T - 1) / T, T>>>(ei, attr, out_vals, E8, E);
}

// round 16
// speedup vs baseline: 1.0925x; 1.0925x over previous
#include <cuda_runtime.h>
#include <math.h>

#define NMAX 100000

__device__ float    g_diag[NMAX];
__device__ unsigned g_deg[NMAX];

// ---------------------------------------------------------------------------
// K1 (heterogeneous): interleaved diag-GEMV blocks and deg+copy blocks.
//   diag block: 8 warps x 2 rows = 16 rows of x (DRAM-bound)
//   deg  block: 256 threads x int4 = 1024 edges (LTS-atomic-bound + copy)
//   Pattern (when GDIAG == 2*GDEG): bid%3<2 -> diag, bid%3==2 -> deg.
// ---------------------------------------------------------------------------
__global__ void __launch_bounds__(256)
k_fused(const float* __restrict__ x,
        const float* __restrict__ w,
        const float* __restrict__ b,
        int n,
        const int* __restrict__ ei,
        float* __restrict__ out_idx,
        int E, int E4, int write_idx,
        int GDIAG, int GDEG, int interleave) {
    int bid = blockIdx.x;
    int is_diag, sub;
    if (interleave) {
        int g3 = bid / 3, r3 = bid - g3 * 3;
        if (bid < 3 * GDEG) {
            if (r3 < 2) { is_diag = 1; sub = g3 * 2 + r3; }
            else        { is_diag = 0; sub = g3; }
        } else {
            is_diag = 1; sub = 2 * GDEG + (bid - 3 * GDEG);
        }
    } else {
        if (bid < GDIAG) { is_diag = 1; sub = bid; }
        else             { is_diag = 0; sub = bid - GDIAG; }
    }

    if (is_diag) {
        // ---------------- diag portion: 2 rows per warp ----------------
        if (sub >= GDIAG) return;
        __shared__ float4 ws[64];
        int t = threadIdx.x;
        if (t < 64) ws[t] = ((const float4*)w)[t];
        __syncthreads();

        int lane = t & 31;
        int warp = sub * 8 + (t >> 5);
        int row0 = warp << 1;
        if (row0 >= n) return;
        bool has1 = (row0 + 1) < n;

        const float4* xr0 = (const float4*)(x + (size_t)row0 * 256);
        const float4* xr1 = (const float4*)(x + (size_t)(row0 + 1) * 256);

        float4 a0 = xr0[lane];
        float4 a1 = xr0[lane + 32];
        float4 c0, c1;
        if (has1) { c0 = xr1[lane]; c1 = xr1[lane + 32]; }
        else      { c0 = make_float4(0,0,0,0); c1 = c0; }

        float4 w0 = ws[lane];
        float4 w1 = ws[lane + 32];

        float s0 = a0.x*w0.x + a0.y*w0.y + a0.z*w0.z + a0.w*w0.w
                 + a1.x*w1.x + a1.y*w1.y + a1.z*w1.z + a1.w*w1.w;
        float s1 = c0.x*w0.x + c0.y*w0.y + c0.z*w0.z + c0.w*w0.w
                 + c1.x*w1.x + c1.y*w1.y + c1.z*w1.z + c1.w*w1.w;

#pragma unroll
        for (int o = 16; o; o >>= 1) {
            s0 += __shfl_xor_sync(0xffffffffu, s0, o);
            s1 += __shfl_xor_sync(0xffffffffu, s1, o);
        }
        if (lane == 0) {
            float bb = b[0];
            g_diag[row0] = 1.0f / (1.0f + expf(-(s0 + bb)));
            if (has1) g_diag[row0 + 1] = 1.0f / (1.0f + expf(-(s1 + bb)));
        }
    } else {
        // ---------------- deg + idx-copy portion ----------------
        int i = sub * 256 + threadIdx.x;
        if (i >= E4) return;
        int4 c = ((const int4*)(ei + E))[i];
        if (write_idx) {
            int4 r = ((const int4*)ei)[i];
            ((float4*)out_idx)[i] =
                make_float4((float)r.x, (float)r.y, (float)r.z, (float)r.w);
            ((float4*)(out_idx + E))[i] =
                make_float4((float)c.x, (float)c.y, (float)c.z, (float)c.w);
        }
        if ((unsigned)c.x < NMAX) atomicAdd(&g_deg[c.x], 1u);
        if ((unsigned)c.y < NMAX) atomicAdd(&g_deg[c.y], 1u);
        if ((unsigned)c.z < NMAX) atomicAdd(&g_deg[c.z], 1u);
        if ((unsigned)c.w < NMAX) atomicAdd(&g_deg[c.w], 1u);
    }
}

// ---------------------------------------------------------------------------
// K2: val[e] = attr[e] * diag[col] * rcp((float)deg[row]); 4 edges/thread.
// ---------------------------------------------------------------------------
__global__ void k_val(const int* __restrict__ ei,
                      const float* __restrict__ attr,
                      float* __restrict__ outv,
                      int E4, int E) {
    int i = blockIdx.x * blockDim.x + threadIdx.x;
    if (i >= E4) return;

    int4 r = ((const int4*)ei)[i];
    int4 c = ((const int4*)(ei + E))[i];
    float4 a = ((const float4*)attr)[i];

    unsigned u0 = ((unsigned)r.x < NMAX) ? g_deg[r.x] : 1u;
    unsigned u1 = ((unsigned)r.y < NMAX) ? g_deg[r.y] : 1u;
    unsigned u2 = ((unsigned)r.z < NMAX) ? g_deg[r.z] : 1u;
    unsigned u3 = ((unsigned)r.w < NMAX) ? g_deg[r.w] : 1u;
    float g0 = ((unsigned)c.x < NMAX) ? g_diag[c.x] : 0.0f;
    float g1 = ((unsigned)c.y < NMAX) ? g_diag[c.y] : 0.0f;
    float g2 = ((unsigned)c.z < NMAX) ? g_diag[c.z] : 0.0f;
    float g3 = ((unsigned)c.w < NMAX) ? g_diag[c.w] : 0.0f;

    float4 v;
    v.x = a.x * g0 * __frcp_rn(__uint2float_rn(u0));
    v.y = a.y * g1 * __frcp_rn(__uint2float_rn(u1));
    v.z = a.z * g2 * __frcp_rn(__uint2float_rn(u2));
    v.w = a.w * g3 * __frcp_rn(__uint2float_rn(u3));
    ((float4*)outv)[i] = v;
}

// ---------------------------------------------------------------------------
static void* g_deg_addr = nullptr;

extern "C" void kernel_launch(void* const* d_in, const int* in_sizes, int n_in,
                              void* d_out, int out_size) {
    const float* x    = (const float*)d_in[0];
    const int*   ei   = (const int*)d_in[1];     // int32 (2, E)
    const float* attr = (const float*)d_in[2];
    const float* w    = (const float*)d_in[3];
    const float* b    = (const float*)d_in[4];

    const int E  = in_sizes[2];
    const int Dd = in_sizes[3];
    const int n  = in_sizes[0] / Dd;

    if (!g_deg_addr) cudaGetSymbolAddress(&g_deg_addr, g_deg);

    float* out = (float*)d_out;
    float* out_vals;
    int write_idx;
    if (out_size >= 3 * E) {      // [edge_index(2E) | vals(E)] as float32
        write_idx = 1;
        out_vals = out + 2 * (size_t)E;
    } else {
        write_idx = 0;
        out_vals = out;
    }

    const int T = 256;
    const int E4 = E >> 2;

    const int GDIAG = (n + 15) / 16;          // 16 rows per diag block
    const int GDEG  = (E4 + T - 1) / T;       // 1024 edges per deg block
    const int interleave = (GDIAG == 2 * GDEG);
    const int GRID = GDIAG + GDEG;

    // zero degree counters via graph memset node (replaces the 4us k_zero)
    cudaMemsetAsync(g_deg_addr, 0, (size_t)n * sizeof(unsigned), 0);

    k_fused<<<GRID, T>>>(x, w, b, n, ei, out, E, E4, write_idx,
                         GDIAG, GDEG, interleave);
    k_val<<<(E4 + T - 1) / T, T>>>(ei, attr, out_vals, E4, E);
}